// round 13
// baseline (speedup 1.0000x reference)
#include <cuda_runtime.h>
#include <cuda_bf16.h>
#include <cuda_fp16.h>
#include <cstdint>

// Problem constants (static per reference)
#define NB   8
#define LQ   2048
#define C    256
#define M    8
#define L    4
#define P    4
#define DH   32
#define S    3840
#define NQ   (NB * LQ)          // 16384
#define MLP  (M * L * P)        // 128

__device__ __constant__ int   c_tlen[4]   = {2048, 1024, 512, 256};
__device__ __constant__ int   c_tstart[4] = {0, 2048, 3072, 3584};
__device__ __constant__ float c_invT[4]   = {1.0f/2048.0f, 1.0f/1024.0f, 1.0f/512.0f, 1.0f/256.0f};

// Scratch (device globals — no allocation allowed)
__device__ __half g_value_h[NB * S * C];  // value in fp16 (consumed only by deform)
__device__ float g_offattn[NQ * 256];     // [0:128)=off raw, [128:256)=attn raw
__device__ float g_deform[NQ * C];

// Pre-converted weights: transposed (n, k=256) fp16; hi plane then lo plane
__device__ __half g_wv[2 * 256 * 256];
__device__ __half g_wq[2 * 256 * 256];
__device__ __half g_wo[2 * 256 * 256];
__device__ float  g_bq[256];

// ===========================================================================
// Helpers
// ===========================================================================
__device__ __forceinline__ uint32_t smem_u32(const void* p) {
    uint32_t a;
    asm("{ .reg .u64 t; cvta.to.shared.u64 t, %1; cvt.u32.u64 %0, t; }" : "=r"(a) : "l"(p));
    return a;
}

__device__ __forceinline__ void ldm_x4(uint32_t* r, uint32_t addr) {
    asm volatile("ldmatrix.sync.aligned.m8n8.x4.shared.b16 {%0,%1,%2,%3}, [%4];"
                 : "=r"(r[0]), "=r"(r[1]), "=r"(r[2]), "=r"(r[3]) : "r"(addr));
}

__device__ __forceinline__ void mma16816(float* c, const uint32_t* a, uint32_t b0, uint32_t b1) {
    asm volatile("mma.sync.aligned.m16n8k16.row.col.f32.f16.f16.f32 "
                 "{%0,%1,%2,%3}, {%4,%5,%6,%7}, {%8,%9}, {%0,%1,%2,%3};"
                 : "+f"(c[0]), "+f"(c[1]), "+f"(c[2]), "+f"(c[3])
                 : "r"(a[0]), "r"(a[1]), "r"(a[2]), "r"(a[3]), "r"(b0), "r"(b1));
}

#define CP_ASYNC16(dst, src) \
    asm volatile("cp.async.cg.shared.global [%0], [%1], 16;" :: "r"(dst), "l"(src))
#define CP_COMMIT() asm volatile("cp.async.commit_group;" ::: "memory")
#define CP_WAIT0()  asm volatile("cp.async.wait_group 0;" ::: "memory")

// ===========================================================================
// Weight pre-conversion: W (k-major fp32) -> W^T (n,256) fp16 hi + fp16 lo.
// ===========================================================================
__global__ __launch_bounds__(256) void convert_weights(
    const float* __restrict__ Wv, const float* __restrict__ Woff,
    const float* __restrict__ Wattn, const float* __restrict__ Wo,
    const float* __restrict__ boff, const float* __restrict__ battn)
{
    int idx = blockIdx.x * 256 + threadIdx.x;
    int mat = idx >> 16;
    int r   = idx & 65535;
    int n   = r >> 8;
    int k   = r & 255;

    float v;
    if (mat == 0)      v = Wv[k * 256 + n];
    else if (mat == 1) v = (n < 128) ? Woff[k * 128 + n] : Wattn[k * 128 + (n - 128)];
    else               v = Wo[k * 256 + n];

    __half h = __float2half_rn(v);
    __half l = __float2half_rn(v - __half2float(h));

    __half* base = (mat == 0) ? g_wv : (mat == 1) ? g_wq : g_wo;
    base[n * 256 + k]         = h;
    base[65536 + n * 256 + k] = l;

    if (mat == 1 && k == 0)
        g_bq[n] = (n < 128) ? boff[n] : battn[n - 128];
}

// ===========================================================================
// Pipelined fp16 2-term tensor-core GEMM, 64x128 tile, dual problem set.
// 4 CTAs/SM (64 regs target): GEMM3's 512 CTAs become one co-resident wave.
// ONE barrier per K-chunk; A single fp16 plane double-buffered; B hi/lo via
// cp.async double buffer.
// ===========================================================================
#define LDS_BF 40
#define SM_A(s) ((s) * 5120)             // single fp16 plane, 64 x 80 B
#define SM_B(s) (10240 + (s) * 20480)    // planes: hi +0, lo +10240
#define GEMM_SMEM 51200

__global__ void __launch_bounds__(256, 4) mma_gemm_bias2(
    const float* __restrict__ A1, const __half* __restrict__ Wt1,
    const float* __restrict__ bias1, float* __restrict__ C1, int nby1, int half1,
    const float* __restrict__ A2, const __half* __restrict__ Wt2,
    const float* __restrict__ bias2, float* __restrict__ C2)
{
    extern __shared__ __align__(128) char smem[];
    const uint32_t sb = smem_u32(smem);

    const int by = blockIdx.y;
    const bool p1 = (by < nby1);
    const float*  A    = p1 ? A1    : A2;
    const __half* Wt   = p1 ? Wt1   : Wt2;
    const float*  bias = p1 ? bias1 : bias2;
    float*        Cout = p1 ? C1    : C2;
    const bool halfOut = p1 && half1;

    const int tid  = threadIdx.x;
    const int wid  = tid >> 5;
    const int lane = tid & 31;
    const int row0 = (p1 ? by : (by - nby1)) * 64;
    const int col0 = blockIdx.x * 128;
    const int wm   = wid & 1;
    const int wn   = wid >> 1;

    float acc[2][4][4];
    #pragma unroll
    for (int i = 0; i < 2; i++)
        #pragma unroll
        for (int j = 0; j < 4; j++)
            #pragma unroll
            for (int r = 0; r < 4; r++) acc[i][j][r] = 0.0f;

    const int a_row    = lane & 15;
    const int a_koff   = (lane >> 4) << 3;
    const int b_rowsel = lane & 7;
    const int b_koff   = ((lane >> 3) & 1) << 3;
    const int b_noff   = (lane >> 4) << 3;

    auto issueB = [&](int k0, int st) {
        #pragma unroll
        for (int i = 0; i < 4; i++) {
            int e   = tid + (i << 8);
            int buf = e >> 9;
            int r   = (e >> 2) & 127;
            int q16 = e & 3;
            const __half* src =
                Wt + (size_t)buf * 65536 + (size_t)(col0 + r) * 256 + k0 + (q16 << 3);
            uint32_t dst = sb + SM_B(st) + buf * 10240 + r * 80 + (q16 << 4);
            CP_ASYNC16(dst, src);
        }
    };

    // Prologue: A chunk 0 -> regs, B chunk 0 -> stage 0
    float4 aReg[2];
    const float* aPtr = A + (size_t)(row0 + (tid >> 3)) * 256 + ((tid & 7) << 2);
    #pragma unroll
    for (int i = 0; i < 2; i++)
        aReg[i] = *reinterpret_cast<const float4*>(aPtr + i * 32 * 256);
    issueB(0, 0);
    CP_COMMIT();

    for (int c = 0; c < 8; c++) {
        // cvt + store A(c) into bufA[c&1]
        const uint32_t aOff = (uint32_t)((tid >> 3) * LDS_BF + ((tid & 7) << 2)) * 2;
        #pragma unroll
        for (int i = 0; i < 2; i++) {
            __half2 p0 = __floats2half2_rn(aReg[i].x, aReg[i].y);
            __half2 p1 = __floats2half2_rn(aReg[i].z, aReg[i].w);
            *reinterpret_cast<uint2*>(smem + SM_A(c & 1) + aOff + i * 32 * LDS_BF * 2) =
                make_uint2(*reinterpret_cast<uint32_t*>(&p0),
                           *reinterpret_cast<uint32_t*>(&p1));
        }

        // Prefetch A(c+1) into regs (hidden under MMA)
        if (c < 7) {
            #pragma unroll
            for (int i = 0; i < 2; i++)
                aReg[i] = *reinterpret_cast<const float4*>(
                    aPtr + ((c + 1) << 5) + i * 32 * 256);
        }

        CP_WAIT0();          // B(c) landed
        __syncthreads();     // A(c)+B(c) visible; all warps done MMA(c-1)

        // Issue B(c+1) after the barrier; overlaps all of MMA(c)
        if (c < 7) {
            issueB((c + 1) << 5, (c + 1) & 1);
            CP_COMMIT();
        }

        const uint32_t uA   = sb + SM_A(c & 1);
        const uint32_t uBhi = sb + SM_B(c & 1);
        const uint32_t uBlo = uBhi + 10240;

        #pragma unroll
        for (int ks = 0; ks < 2; ks++) {
            const int kb = ks << 4;

            uint32_t ah[2][4], bh[2][4], bl[2][4];
            #pragma unroll
            for (int mi = 0; mi < 2; mi++) {
                uint32_t addr = uA + (uint32_t)((wm * 32 + mi * 16 + a_row) * LDS_BF + kb + a_koff) * 2;
                ldm_x4(ah[mi], addr);
            }
            #pragma unroll
            for (int g = 0; g < 2; g++) {
                uint32_t roff = (uint32_t)((wn * 32 + g * 16 + b_noff + b_rowsel) * LDS_BF + kb + b_koff) * 2;
                ldm_x4(bh[g], uBhi + roff);
                ldm_x4(bl[g], uBlo + roff);
            }
            // term 1: A * B_hi
            #pragma unroll
            for (int mi = 0; mi < 2; mi++)
                #pragma unroll
                for (int ni = 0; ni < 4; ni++) {
                    const uint32_t* bb = bh[ni >> 1];
                    mma16816(acc[mi][ni], ah[mi], bb[(ni & 1) * 2], bb[(ni & 1) * 2 + 1]);
                }
            // term 2: A * B_lo
            #pragma unroll
            for (int mi = 0; mi < 2; mi++)
                #pragma unroll
                for (int ni = 0; ni < 4; ni++) {
                    const uint32_t* bb = bl[ni >> 1];
                    mma16816(acc[mi][ni], ah[mi], bb[(ni & 1) * 2], bb[(ni & 1) * 2 + 1]);
                }
        }
    }

    const int grp   = lane >> 2;
    const int cpair = (lane & 3) << 1;
    if (halfOut) {
        __half* Ch = (__half*)Cout;
        #pragma unroll
        for (int mi = 0; mi < 2; mi++) {
            #pragma unroll
            for (int ni = 0; ni < 4; ni++) {
                int colg = col0 + wn * 32 + ni * 8 + cpair;
                float b0 = bias[colg], b1 = bias[colg + 1];
                int rowg = row0 + wm * 32 + mi * 16 + grp;
                __half2 o0 = __floats2half2_rn(acc[mi][ni][0] + b0, acc[mi][ni][1] + b1);
                __half2 o1 = __floats2half2_rn(acc[mi][ni][2] + b0, acc[mi][ni][3] + b1);
                *reinterpret_cast<__half2*>(Ch + (size_t)rowg * 256 + colg) = o0;
                *reinterpret_cast<__half2*>(Ch + (size_t)(rowg + 8) * 256 + colg) = o1;
            }
        }
    } else {
        #pragma unroll
        for (int mi = 0; mi < 2; mi++) {
            #pragma unroll
            for (int ni = 0; ni < 4; ni++) {
                int colg = col0 + wn * 32 + ni * 8 + cpair;
                float b0 = bias[colg], b1 = bias[colg + 1];
                int rowg = row0 + wm * 32 + mi * 16 + grp;
                float2 o0 = make_float2(acc[mi][ni][0] + b0, acc[mi][ni][1] + b1);
                float2 o1 = make_float2(acc[mi][ni][2] + b0, acc[mi][ni][3] + b1);
                *reinterpret_cast<float2*>(Cout + (size_t)rowg * 256 + colg) = o0;
                *reinterpret_cast<float2*>(Cout + (size_t)(rowg + 8) * 256 + colg) = o1;
            }
        }
    }
}

// ---------------------------------------------------------------------------
// Fused softmax + loc + deformable gather, FOUR queries per 512-thread block.
// Phase 1: all 512 threads, one per (query, head, point). Phase 2: 16 warps;
// warp w = head (w&7), query-subset (w>>3); each warp does 2 queries with
// two independent accumulators each (dependent chain 32 -> 16 FMAs).
// ---------------------------------------------------------------------------
__global__ __launch_bounds__(512) void deform_fused(
    const float* __restrict__ refp,
    float* __restrict__ out_loc,
    float* __restrict__ out_attn)
{
    const int q0 = blockIdx.x << 2;
    const int n  = q0 >> 11;         // all 4 queries share the batch (LQ % 4 == 0)
    const int t  = threadIdx.x;

    __shared__ int4 sPack[512];

    {
        const int q  = q0 + (t >> 7);
        const int tt = t & 127;
        const int l  = (tt >> 2) & 3;
        const float* row = g_offattn + (size_t)q * 256;
        float off  = row[tt];
        float araw = row[128 + tt];

        float mx = araw;
        #pragma unroll
        for (int d = 1; d < 16; d <<= 1)
            mx = fmaxf(mx, __shfl_xor_sync(0xffffffffu, mx, d));
        float e = __expf(araw - mx);
        float s = e;
        #pragma unroll
        for (int d = 1; d < 16; d <<= 1)
            s += __shfl_xor_sync(0xffffffffu, s, d);

        float attn = e / s;
        float loc  = refp[(size_t)q * 4 + l] + off * c_invT[l];

        out_loc [(size_t)q * 128 + tt] = loc;
        out_attn[(size_t)q * 128 + tt] = attn;

        const int Ti = c_tlen[l];
        const int st = c_tstart[l];
        float pos  = loc * (float)Ti - 0.5f;
        float x0f  = floorf(pos);
        float frac = pos - x0f;
        int   x0   = (int)x0f;

        float w0 = (x0 >= 0 && x0 < Ti)         ? (1.0f - frac) * attn : 0.0f;
        float w1 = (x0 + 1 >= 0 && x0 + 1 < Ti) ? frac * attn          : 0.0f;

        int i0 = min(max(x0, 0), Ti - 1) + st;
        int i1 = min(max(x0 + 1, 0), Ti - 1) + st;

        sPack[t] = make_int4(__float_as_int(w0), __float_as_int(w1),
                             i0 << 9, i1 << 9);   // byte offsets (half row = 512 B)
    }
    __syncthreads();

    const int w    = t >> 5;
    const int m    = w & 7;
    const int qsub = w >> 3;          // 0 or 1
    const int d    = t & 31;
    const char* base = (const char*)(g_value_h + (size_t)n * S * C + m * DH + d);

    #pragma unroll
    for (int qi = 0; qi < 2; qi++) {
        const int ql = qsub * 2 + qi;                 // local query 0..3
        const int4* pk = &sPack[(ql << 7) + (m << 4)];
        float accA = 0.0f, accB = 0.0f;
        #pragma unroll
        for (int lp = 0; lp < 16; lp += 2) {
            int4 pa = pk[lp];
            int4 pb = pk[lp + 1];
            float a0 = __half2float(*reinterpret_cast<const __half*>(base + pa.z));
            float a1 = __half2float(*reinterpret_cast<const __half*>(base + pa.w));
            float b0 = __half2float(*reinterpret_cast<const __half*>(base + pb.z));
            float b1 = __half2float(*reinterpret_cast<const __half*>(base + pb.w));
            accA = fmaf(__int_as_float(pa.x), a0, accA);
            accA = fmaf(__int_as_float(pa.y), a1, accA);
            accB = fmaf(__int_as_float(pb.x), b0, accB);
            accB = fmaf(__int_as_float(pb.y), b1, accB);
        }
        g_deform[(size_t)(q0 + ql) * C + m * DH + d] = accA + accB;
    }
}

// ---------------------------------------------------------------------------
extern "C" void kernel_launch(void* const* d_in, const int* in_sizes, int n_in,
                              void* d_out, int out_size)
{
    const float* query  = (const float*)d_in[0];
    const float* refp   = (const float*)d_in[1];
    const float* inpf   = (const float*)d_in[2];
    const float* W_off  = (const float*)d_in[5];
    const float* b_off  = (const float*)d_in[6];
    const float* W_attn = (const float*)d_in[7];
    const float* b_attn = (const float*)d_in[8];
    const float* W_val  = (const float*)d_in[9];
    const float* b_val  = (const float*)d_in[10];
    const float* W_out  = (const float*)d_in[11];
    const float* b_out  = (const float*)d_in[12];

    float* out      = (float*)d_out;
    float* out_loc  = out + (size_t)NQ * C;
    float* out_attn = out_loc + (size_t)NQ * MLP;

    float *pOffattn, *pDeform, *pBq;
    __half *pValueH, *pWv, *pWq, *pWo;
    cudaGetSymbolAddress((void**)&pValueH,  g_value_h);
    cudaGetSymbolAddress((void**)&pOffattn, g_offattn);
    cudaGetSymbolAddress((void**)&pDeform,  g_deform);
    cudaGetSymbolAddress((void**)&pWv,      g_wv);
    cudaGetSymbolAddress((void**)&pWq,      g_wq);
    cudaGetSymbolAddress((void**)&pWo,      g_wo);
    cudaGetSymbolAddress((void**)&pBq,      g_bq);

    cudaFuncSetAttribute(mma_gemm_bias2, cudaFuncAttributeMaxDynamicSharedMemorySize, GEMM_SMEM);

    // 0) pre-convert weights to fp16 hi/lo
    convert_weights<<<768, 256>>>(W_val, W_off, W_attn, W_out, b_off, b_attn);

    // 1+2) value GEMM (480 x 64-row blocks, fp16 out) + off/attn GEMM (256 blocks)
    mma_gemm_bias2<<<dim3(2, 736), 256, GEMM_SMEM>>>(
        inpf, pWv, b_val, (float*)pValueH, 480, 1,
        query, pWq, pBq, pOffattn);

    // 3) fused softmax + loc + deformable gather (fp16 value, 4 queries/block)
    deform_fused<<<NQ / 4, 512>>>(refp, out_loc, out_attn);

    // 4) out = g_deform @ W_out + b_out  (256 x 64-row blocks, single wave)
    mma_gemm_bias2<<<dim3(2, 256), 256, GEMM_SMEM>>>(
        pDeform, pWo, b_out, out, 256, 0,
        pDeform, pWo, b_out, out);
}

// round 14
// speedup vs baseline: 1.1311x; 1.1311x over previous
#include <cuda_runtime.h>
#include <cuda_bf16.h>
#include <cuda_fp16.h>
#include <cstdint>

// Problem constants (static per reference)
#define NB   8
#define LQ   2048
#define C    256
#define M    8
#define L    4
#define P    4
#define DH   32
#define S    3840
#define NQ   (NB * LQ)          // 16384
#define MLP  (M * L * P)        // 128

__device__ __constant__ int   c_tlen[4]   = {2048, 1024, 512, 256};
__device__ __constant__ int   c_tstart[4] = {0, 2048, 3072, 3584};
__device__ __constant__ float c_invT[4]   = {1.0f/2048.0f, 1.0f/1024.0f, 1.0f/512.0f, 1.0f/256.0f};

// Scratch (device globals — no allocation allowed)
__device__ __half g_value_h[NB * S * C];  // value in fp16 (consumed only by deform)
__device__ float g_offattn[NQ * 256];     // [0:128)=off raw, [128:256)=attn raw
__device__ float g_deform[NQ * C];

// Pre-converted weights: transposed (n, k=256) fp16; hi plane then lo plane
__device__ __half g_wv[2 * 256 * 256];
__device__ __half g_wq[2 * 256 * 256];
__device__ __half g_wo[2 * 256 * 256];
__device__ float  g_bq[256];

// ===========================================================================
// Helpers
// ===========================================================================
__device__ __forceinline__ uint32_t smem_u32(const void* p) {
    uint32_t a;
    asm("{ .reg .u64 t; cvta.to.shared.u64 t, %1; cvt.u32.u64 %0, t; }" : "=r"(a) : "l"(p));
    return a;
}

__device__ __forceinline__ void ldm_x4(uint32_t* r, uint32_t addr) {
    asm volatile("ldmatrix.sync.aligned.m8n8.x4.shared.b16 {%0,%1,%2,%3}, [%4];"
                 : "=r"(r[0]), "=r"(r[1]), "=r"(r[2]), "=r"(r[3]) : "r"(addr));
}

__device__ __forceinline__ void mma16816(float* c, const uint32_t* a, uint32_t b0, uint32_t b1) {
    asm volatile("mma.sync.aligned.m16n8k16.row.col.f32.f16.f16.f32 "
                 "{%0,%1,%2,%3}, {%4,%5,%6,%7}, {%8,%9}, {%0,%1,%2,%3};"
                 : "+f"(c[0]), "+f"(c[1]), "+f"(c[2]), "+f"(c[3])
                 : "r"(a[0]), "r"(a[1]), "r"(a[2]), "r"(a[3]), "r"(b0), "r"(b1));
}

#define CP_ASYNC16(dst, src) \
    asm volatile("cp.async.cg.shared.global [%0], [%1], 16;" :: "r"(dst), "l"(src))
#define CP_COMMIT() asm volatile("cp.async.commit_group;" ::: "memory")
#define CP_WAIT0()  asm volatile("cp.async.wait_group 0;" ::: "memory")

// ===========================================================================
// Weight pre-conversion: W (k-major fp32) -> W^T (n,256) fp16 hi + fp16 lo.
// ===========================================================================
__global__ __launch_bounds__(256) void convert_weights(
    const float* __restrict__ Wv, const float* __restrict__ Woff,
    const float* __restrict__ Wattn, const float* __restrict__ Wo,
    const float* __restrict__ boff, const float* __restrict__ battn)
{
    int idx = blockIdx.x * 256 + threadIdx.x;
    int mat = idx >> 16;
    int r   = idx & 65535;
    int n   = r >> 8;
    int k   = r & 255;

    float v;
    if (mat == 0)      v = Wv[k * 256 + n];
    else if (mat == 1) v = (n < 128) ? Woff[k * 128 + n] : Wattn[k * 128 + (n - 128)];
    else               v = Wo[k * 256 + n];

    __half h = __float2half_rn(v);
    __half l = __float2half_rn(v - __half2float(h));

    __half* base = (mat == 0) ? g_wv : (mat == 1) ? g_wq : g_wo;
    base[n * 256 + k]         = h;
    base[65536 + n * 256 + k] = l;

    if (mat == 1 && k == 0)
        g_bq[n] = (n < 128) ? boff[n] : battn[n - 128];
}

// ===========================================================================
// Pipelined fp16 2-term tensor-core GEMM, 64x128 tile, dual problem set.
// __launch_bounds__(256,3): 80 regs is this kernel's natural operating point
// (forcing 64 regs in R13 regressed GEMM3 23.0 -> 28.5 us).
// ONE barrier per K-chunk; A single fp16 plane double-buffered; B hi/lo via
// cp.async double buffer.
// ===========================================================================
#define LDS_BF 40
#define SM_A(s) ((s) * 5120)             // single fp16 plane, 64 x 80 B
#define SM_B(s) (10240 + (s) * 20480)    // planes: hi +0, lo +10240
#define GEMM_SMEM 51200

__global__ void __launch_bounds__(256, 3) mma_gemm_bias2(
    const float* __restrict__ A1, const __half* __restrict__ Wt1,
    const float* __restrict__ bias1, float* __restrict__ C1, int nby1, int half1,
    const float* __restrict__ A2, const __half* __restrict__ Wt2,
    const float* __restrict__ bias2, float* __restrict__ C2)
{
    extern __shared__ __align__(128) char smem[];
    const uint32_t sb = smem_u32(smem);

    const int by = blockIdx.y;
    const bool p1 = (by < nby1);
    const float*  A    = p1 ? A1    : A2;
    const __half* Wt   = p1 ? Wt1   : Wt2;
    const float*  bias = p1 ? bias1 : bias2;
    float*        Cout = p1 ? C1    : C2;
    const bool halfOut = p1 && half1;

    const int tid  = threadIdx.x;
    const int wid  = tid >> 5;
    const int lane = tid & 31;
    const int row0 = (p1 ? by : (by - nby1)) * 64;
    const int col0 = blockIdx.x * 128;
    const int wm   = wid & 1;
    const int wn   = wid >> 1;

    float acc[2][4][4];
    #pragma unroll
    for (int i = 0; i < 2; i++)
        #pragma unroll
        for (int j = 0; j < 4; j++)
            #pragma unroll
            for (int r = 0; r < 4; r++) acc[i][j][r] = 0.0f;

    const int a_row    = lane & 15;
    const int a_koff   = (lane >> 4) << 3;
    const int b_rowsel = lane & 7;
    const int b_koff   = ((lane >> 3) & 1) << 3;
    const int b_noff   = (lane >> 4) << 3;

    auto issueB = [&](int k0, int st) {
        #pragma unroll
        for (int i = 0; i < 4; i++) {
            int e   = tid + (i << 8);
            int buf = e >> 9;
            int r   = (e >> 2) & 127;
            int q16 = e & 3;
            const __half* src =
                Wt + (size_t)buf * 65536 + (size_t)(col0 + r) * 256 + k0 + (q16 << 3);
            uint32_t dst = sb + SM_B(st) + buf * 10240 + r * 80 + (q16 << 4);
            CP_ASYNC16(dst, src);
        }
    };

    // Prologue: A chunk 0 -> regs, B chunk 0 -> stage 0
    float4 aReg[2];
    #pragma unroll
    for (int i = 0; i < 2; i++) {
        int e = tid + (i << 8);
        int r = e >> 3;
        int kk = (e & 7) << 2;
        aReg[i] = *reinterpret_cast<const float4*>(A + (size_t)(row0 + r) * 256 + kk);
    }
    issueB(0, 0);
    CP_COMMIT();

    for (int c = 0; c < 8; c++) {
        // cvt + store A(c) into bufA[c&1]
        #pragma unroll
        for (int i = 0; i < 2; i++) {
            int e = tid + (i << 8);
            int r = e >> 3;
            int kk = (e & 7) << 2;
            __half2 p0 = __floats2half2_rn(aReg[i].x, aReg[i].y);
            __half2 p1 = __floats2half2_rn(aReg[i].z, aReg[i].w);
            uint32_t off = (uint32_t)(r * LDS_BF + kk) * 2;
            *reinterpret_cast<uint2*>(smem + SM_A(c & 1) + off) =
                make_uint2(*reinterpret_cast<uint32_t*>(&p0),
                           *reinterpret_cast<uint32_t*>(&p1));
        }

        // Prefetch A(c+1) into regs (hidden under MMA)
        if (c < 7) {
            const int k0n = (c + 1) << 5;
            #pragma unroll
            for (int i = 0; i < 2; i++) {
                int e = tid + (i << 8);
                int r = e >> 3;
                int kk = (e & 7) << 2;
                aReg[i] = *reinterpret_cast<const float4*>(
                    A + (size_t)(row0 + r) * 256 + k0n + kk);
            }
        }

        CP_WAIT0();          // B(c) landed
        __syncthreads();     // A(c)+B(c) visible; all warps done MMA(c-1)

        // Issue B(c+1) after the barrier; overlaps all of MMA(c)
        if (c < 7) {
            issueB((c + 1) << 5, (c + 1) & 1);
            CP_COMMIT();
        }

        const uint32_t uA   = sb + SM_A(c & 1);
        const uint32_t uBhi = sb + SM_B(c & 1);
        const uint32_t uBlo = uBhi + 10240;

        #pragma unroll
        for (int ks = 0; ks < 2; ks++) {
            const int kb = ks << 4;

            uint32_t ah[2][4], bh[2][4], bl[2][4];
            #pragma unroll
            for (int mi = 0; mi < 2; mi++) {
                uint32_t addr = uA + (uint32_t)((wm * 32 + mi * 16 + a_row) * LDS_BF + kb + a_koff) * 2;
                ldm_x4(ah[mi], addr);
            }
            #pragma unroll
            for (int g = 0; g < 2; g++) {
                uint32_t roff = (uint32_t)((wn * 32 + g * 16 + b_noff + b_rowsel) * LDS_BF + kb + b_koff) * 2;
                ldm_x4(bh[g], uBhi + roff);
                ldm_x4(bl[g], uBlo + roff);
            }
            // term 1: A * B_hi
            #pragma unroll
            for (int mi = 0; mi < 2; mi++)
                #pragma unroll
                for (int ni = 0; ni < 4; ni++) {
                    const uint32_t* bb = bh[ni >> 1];
                    mma16816(acc[mi][ni], ah[mi], bb[(ni & 1) * 2], bb[(ni & 1) * 2 + 1]);
                }
            // term 2: A * B_lo
            #pragma unroll
            for (int mi = 0; mi < 2; mi++)
                #pragma unroll
                for (int ni = 0; ni < 4; ni++) {
                    const uint32_t* bb = bl[ni >> 1];
                    mma16816(acc[mi][ni], ah[mi], bb[(ni & 1) * 2], bb[(ni & 1) * 2 + 1]);
                }
        }
    }

    const int grp   = lane >> 2;
    const int cpair = (lane & 3) << 1;
    if (halfOut) {
        __half* Ch = (__half*)Cout;
        #pragma unroll
        for (int mi = 0; mi < 2; mi++) {
            #pragma unroll
            for (int ni = 0; ni < 4; ni++) {
                int colg = col0 + wn * 32 + ni * 8 + cpair;
                float b0 = bias[colg], b1 = bias[colg + 1];
                int rowg = row0 + wm * 32 + mi * 16 + grp;
                __half2 o0 = __floats2half2_rn(acc[mi][ni][0] + b0, acc[mi][ni][1] + b1);
                __half2 o1 = __floats2half2_rn(acc[mi][ni][2] + b0, acc[mi][ni][3] + b1);
                *reinterpret_cast<__half2*>(Ch + (size_t)rowg * 256 + colg) = o0;
                *reinterpret_cast<__half2*>(Ch + (size_t)(rowg + 8) * 256 + colg) = o1;
            }
        }
    } else {
        #pragma unroll
        for (int mi = 0; mi < 2; mi++) {
            #pragma unroll
            for (int ni = 0; ni < 4; ni++) {
                int colg = col0 + wn * 32 + ni * 8 + cpair;
                float b0 = bias[colg], b1 = bias[colg + 1];
                int rowg = row0 + wm * 32 + mi * 16 + grp;
                float2 o0 = make_float2(acc[mi][ni][0] + b0, acc[mi][ni][1] + b1);
                float2 o1 = make_float2(acc[mi][ni][2] + b0, acc[mi][ni][3] + b1);
                *reinterpret_cast<float2*>(Cout + (size_t)rowg * 256 + colg) = o0;
                *reinterpret_cast<float2*>(Cout + (size_t)(rowg + 8) * 256 + colg) = o1;
            }
        }
    }
}

// ---------------------------------------------------------------------------
// Fused softmax + loc + deformable gather, FOUR queries per 512-thread block.
// Phase 1: all 512 threads, one per (query, head, point). Phase 2: 16 warps;
// warp w = head (w&7), query-subset (w>>3); each warp does 2 queries with
// two independent accumulators each (dependent chain 32 -> 16 FMAs).
// ---------------------------------------------------------------------------
__global__ __launch_bounds__(512) void deform_fused(
    const float* __restrict__ refp,
    float* __restrict__ out_loc,
    float* __restrict__ out_attn)
{
    const int q0 = blockIdx.x << 2;
    const int n  = q0 >> 11;         // all 4 queries share the batch (LQ % 4 == 0)
    const int t  = threadIdx.x;

    __shared__ int4 sPack[512];

    {
        const int q  = q0 + (t >> 7);
        const int tt = t & 127;
        const int l  = (tt >> 2) & 3;
        const float* row = g_offattn + (size_t)q * 256;
        float off  = row[tt];
        float araw = row[128 + tt];

        float mx = araw;
        #pragma unroll
        for (int d = 1; d < 16; d <<= 1)
            mx = fmaxf(mx, __shfl_xor_sync(0xffffffffu, mx, d));
        float e = __expf(araw - mx);
        float s = e;
        #pragma unroll
        for (int d = 1; d < 16; d <<= 1)
            s += __shfl_xor_sync(0xffffffffu, s, d);

        float attn = e / s;
        float loc  = refp[(size_t)q * 4 + l] + off * c_invT[l];

        out_loc [(size_t)q * 128 + tt] = loc;
        out_attn[(size_t)q * 128 + tt] = attn;

        const int Ti = c_tlen[l];
        const int st = c_tstart[l];
        float pos  = loc * (float)Ti - 0.5f;
        float x0f  = floorf(pos);
        float frac = pos - x0f;
        int   x0   = (int)x0f;

        float w0 = (x0 >= 0 && x0 < Ti)         ? (1.0f - frac) * attn : 0.0f;
        float w1 = (x0 + 1 >= 0 && x0 + 1 < Ti) ? frac * attn          : 0.0f;

        int i0 = min(max(x0, 0), Ti - 1) + st;
        int i1 = min(max(x0 + 1, 0), Ti - 1) + st;

        sPack[t] = make_int4(__float_as_int(w0), __float_as_int(w1),
                             i0 << 9, i1 << 9);   // byte offsets (half row = 512 B)
    }
    __syncthreads();

    const int w    = t >> 5;
    const int m    = w & 7;
    const int qsub = w >> 3;          // 0 or 1
    const int d    = t & 31;
    const char* base = (const char*)(g_value_h + (size_t)n * S * C + m * DH + d);

    #pragma unroll
    for (int qi = 0; qi < 2; qi++) {
        const int ql = qsub * 2 + qi;                 // local query 0..3
        const int4* pk = &sPack[(ql << 7) + (m << 4)];
        float accA = 0.0f, accB = 0.0f;
        #pragma unroll
        for (int lp = 0; lp < 16; lp += 2) {
            int4 pa = pk[lp];
            int4 pb = pk[lp + 1];
            float a0 = __half2float(*reinterpret_cast<const __half*>(base + pa.z));
            float a1 = __half2float(*reinterpret_cast<const __half*>(base + pa.w));
            float b0 = __half2float(*reinterpret_cast<const __half*>(base + pb.z));
            float b1 = __half2float(*reinterpret_cast<const __half*>(base + pb.w));
            accA = fmaf(__int_as_float(pa.x), a0, accA);
            accA = fmaf(__int_as_float(pa.y), a1, accA);
            accB = fmaf(__int_as_float(pb.x), b0, accB);
            accB = fmaf(__int_as_float(pb.y), b1, accB);
        }
        g_deform[(size_t)(q0 + ql) * C + m * DH + d] = accA + accB;
    }
}

// ---------------------------------------------------------------------------
extern "C" void kernel_launch(void* const* d_in, const int* in_sizes, int n_in,
                              void* d_out, int out_size)
{
    const float* query  = (const float*)d_in[0];
    const float* refp   = (const float*)d_in[1];
    const float* inpf   = (const float*)d_in[2];
    const float* W_off  = (const float*)d_in[5];
    const float* b_off  = (const float*)d_in[6];
    const float* W_attn = (const float*)d_in[7];
    const float* b_attn = (const float*)d_in[8];
    const float* W_val  = (const float*)d_in[9];
    const float* b_val  = (const float*)d_in[10];
    const float* W_out  = (const float*)d_in[11];
    const float* b_out  = (const float*)d_in[12];

    float* out      = (float*)d_out;
    float* out_loc  = out + (size_t)NQ * C;
    float* out_attn = out_loc + (size_t)NQ * MLP;

    float *pOffattn, *pDeform, *pBq;
    __half *pValueH, *pWv, *pWq, *pWo;
    cudaGetSymbolAddress((void**)&pValueH,  g_value_h);
    cudaGetSymbolAddress((void**)&pOffattn, g_offattn);
    cudaGetSymbolAddress((void**)&pDeform,  g_deform);
    cudaGetSymbolAddress((void**)&pWv,      g_wv);
    cudaGetSymbolAddress((void**)&pWq,      g_wq);
    cudaGetSymbolAddress((void**)&pWo,      g_wo);
    cudaGetSymbolAddress((void**)&pBq,      g_bq);

    cudaFuncSetAttribute(mma_gemm_bias2, cudaFuncAttributeMaxDynamicSharedMemorySize, GEMM_SMEM);

    // 0) pre-convert weights to fp16 hi/lo
    convert_weights<<<768, 256>>>(W_val, W_off, W_attn, W_out, b_off, b_attn);

    // 1+2) value GEMM (480 x 64-row blocks, fp16 out) + off/attn GEMM (256 blocks)
    mma_gemm_bias2<<<dim3(2, 736), 256, GEMM_SMEM>>>(
        inpf, pWv, b_val, (float*)pValueH, 480, 1,
        query, pWq, pBq, pOffattn);

    // 3) fused softmax + loc + deformable gather (fp16 value, 4 queries/block)
    deform_fused<<<NQ / 4, 512>>>(refp, out_loc, out_attn);

    // 4) out = g_deform @ W_out + b_out  (256 x 64-row blocks)
    mma_gemm_bias2<<<dim3(2, 256), 256, GEMM_SMEM>>>(
        pDeform, pWo, b_out, out, 256, 0,
        pDeform, pWo, b_out, out);
}

// round 15
// speedup vs baseline: 1.2079x; 1.0680x over previous
#include <cuda_runtime.h>
#include <cuda_bf16.h>
#include <cuda_fp16.h>
#include <cstdint>

// Problem constants (static per reference)
#define NB   8
#define LQ   2048
#define C    256
#define M    8
#define L    4
#define P    4
#define DH   32
#define S    3840
#define NQ   (NB * LQ)          // 16384
#define MLP  (M * L * P)        // 128

__device__ __constant__ int   c_tlen[4]   = {2048, 1024, 512, 256};
__device__ __constant__ int   c_tstart[4] = {0, 2048, 3072, 3584};
__device__ __constant__ float c_invT[4]   = {1.0f/2048.0f, 1.0f/1024.0f, 1.0f/512.0f, 1.0f/256.0f};

// Scratch (device globals — no allocation allowed)
__device__ __half g_value_h[NB * S * C];  // value in fp16 (consumed only by deform)
__device__ float g_offattn[NQ * 256];     // [0:128)=off raw, [128:256)=attn raw
__device__ float g_deform[NQ * C];

// Pre-converted weights: transposed (n, k=256) fp16; hi plane then lo plane
__device__ __half g_wv[2 * 256 * 256];
__device__ __half g_wq[2 * 256 * 256];
__device__ __half g_wo[2 * 256 * 256];
__device__ float  g_bq[256];

// ===========================================================================
// Helpers
// ===========================================================================
__device__ __forceinline__ uint32_t smem_u32(const void* p) {
    uint32_t a;
    asm("{ .reg .u64 t; cvta.to.shared.u64 t, %1; cvt.u32.u64 %0, t; }" : "=r"(a) : "l"(p));
    return a;
}

__device__ __forceinline__ void ldm_x4(uint32_t* r, uint32_t addr) {
    asm volatile("ldmatrix.sync.aligned.m8n8.x4.shared.b16 {%0,%1,%2,%3}, [%4];"
                 : "=r"(r[0]), "=r"(r[1]), "=r"(r[2]), "=r"(r[3]) : "r"(addr));
}

__device__ __forceinline__ void mma16816(float* c, const uint32_t* a, uint32_t b0, uint32_t b1) {
    asm volatile("mma.sync.aligned.m16n8k16.row.col.f32.f16.f16.f32 "
                 "{%0,%1,%2,%3}, {%4,%5,%6,%7}, {%8,%9}, {%0,%1,%2,%3};"
                 : "+f"(c[0]), "+f"(c[1]), "+f"(c[2]), "+f"(c[3])
                 : "r"(a[0]), "r"(a[1]), "r"(a[2]), "r"(a[3]), "r"(b0), "r"(b1));
}

#define CP_ASYNC16(dst, src) \
    asm volatile("cp.async.cg.shared.global [%0], [%1], 16;" :: "r"(dst), "l"(src))
#define CP_COMMIT() asm volatile("cp.async.commit_group;" ::: "memory")
#define CP_WAIT0()  asm volatile("cp.async.wait_group 0;" ::: "memory")

// ===========================================================================
// Weight pre-conversion: W (k-major fp32) -> W^T (n,256) fp16 hi + fp16 lo.
// ===========================================================================
__global__ __launch_bounds__(256) void convert_weights(
    const float* __restrict__ Wv, const float* __restrict__ Woff,
    const float* __restrict__ Wattn, const float* __restrict__ Wo,
    const float* __restrict__ boff, const float* __restrict__ battn)
{
    int idx = blockIdx.x * 256 + threadIdx.x;
    int mat = idx >> 16;
    int r   = idx & 65535;
    int n   = r >> 8;
    int k   = r & 255;

    float v;
    if (mat == 0)      v = Wv[k * 256 + n];
    else if (mat == 1) v = (n < 128) ? Woff[k * 128 + n] : Wattn[k * 128 + (n - 128)];
    else               v = Wo[k * 256 + n];

    __half h = __float2half_rn(v);
    __half l = __float2half_rn(v - __half2float(h));

    __half* base = (mat == 0) ? g_wv : (mat == 1) ? g_wq : g_wo;
    base[n * 256 + k]         = h;
    base[65536 + n * 256 + k] = l;

    if (mat == 1 && k == 0)
        g_bq[n] = (n < 128) ? boff[n] : battn[n - 128];
}

// ===========================================================================
// Pipelined fp16 tensor-core GEMM, 64x128 tile, dual problem set.
// terms1: MMA terms for problem 1 (1 = A@B_hi only; 2 = A@(B_hi+B_lo)).
// Problem 2 is always 2-term. (256,3): 80 regs is the natural operating
// point (R13: forcing 64 regs regressed GEMM3 23.0 -> 28.5 us).
// ONE barrier per K-chunk; A single fp16 plane double-buffered; B via
// cp.async double buffer (lo plane skipped when 1-term).
// ===========================================================================
#define LDS_BF 40
#define SM_A(s) ((s) * 5120)             // single fp16 plane, 64 x 80 B
#define SM_B(s) (10240 + (s) * 20480)    // planes: hi +0, lo +10240
#define GEMM_SMEM 51200

__global__ void __launch_bounds__(256, 3) mma_gemm_bias2(
    const float* __restrict__ A1, const __half* __restrict__ Wt1,
    const float* __restrict__ bias1, float* __restrict__ C1, int nby1,
    int half1, int terms1,
    const float* __restrict__ A2, const __half* __restrict__ Wt2,
    const float* __restrict__ bias2, float* __restrict__ C2)
{
    extern __shared__ __align__(128) char smem[];
    const uint32_t sb = smem_u32(smem);

    const int by = blockIdx.y;
    const bool p1 = (by < nby1);
    const float*  A    = p1 ? A1    : A2;
    const __half* Wt   = p1 ? Wt1   : Wt2;
    const float*  bias = p1 ? bias1 : bias2;
    float*        Cout = p1 ? C1    : C2;
    const bool halfOut = p1 && half1;
    const bool two     = !p1 || (terms1 == 2);   // 2-term MMA?

    const int tid  = threadIdx.x;
    const int wid  = tid >> 5;
    const int lane = tid & 31;
    const int row0 = (p1 ? by : (by - nby1)) * 64;
    const int col0 = blockIdx.x * 128;
    const int wm   = wid & 1;
    const int wn   = wid >> 1;

    float acc[2][4][4];
    #pragma unroll
    for (int i = 0; i < 2; i++)
        #pragma unroll
        for (int j = 0; j < 4; j++)
            #pragma unroll
            for (int r = 0; r < 4; r++) acc[i][j][r] = 0.0f;

    const int a_row    = lane & 15;
    const int a_koff   = (lane >> 4) << 3;
    const int b_rowsel = lane & 7;
    const int b_koff   = ((lane >> 3) & 1) << 3;
    const int b_noff   = (lane >> 4) << 3;

    const int nld = two ? 4 : 2;     // cp.async quads per thread (hi+lo or hi)
    auto issueB = [&](int k0, int st) {
        #pragma unroll 4
        for (int i = 0; i < nld; i++) {
            int e   = tid + (i << 8);
            int buf = e >> 9;               // 0 hi, 1 lo
            int r   = (e >> 2) & 127;
            int q16 = e & 3;
            const __half* src =
                Wt + (size_t)buf * 65536 + (size_t)(col0 + r) * 256 + k0 + (q16 << 3);
            uint32_t dst = sb + SM_B(st) + buf * 10240 + r * 80 + (q16 << 4);
            CP_ASYNC16(dst, src);
        }
    };

    // Prologue: A chunk 0 -> regs, B chunk 0 -> stage 0
    float4 aReg[2];
    #pragma unroll
    for (int i = 0; i < 2; i++) {
        int e = tid + (i << 8);
        int r = e >> 3;
        int kk = (e & 7) << 2;
        aReg[i] = *reinterpret_cast<const float4*>(A + (size_t)(row0 + r) * 256 + kk);
    }
    issueB(0, 0);
    CP_COMMIT();

    for (int c = 0; c < 8; c++) {
        // cvt + store A(c) into bufA[c&1]
        #pragma unroll
        for (int i = 0; i < 2; i++) {
            int e = tid + (i << 8);
            int r = e >> 3;
            int kk = (e & 7) << 2;
            __half2 p0 = __floats2half2_rn(aReg[i].x, aReg[i].y);
            __half2 p1x = __floats2half2_rn(aReg[i].z, aReg[i].w);
            uint32_t off = (uint32_t)(r * LDS_BF + kk) * 2;
            *reinterpret_cast<uint2*>(smem + SM_A(c & 1) + off) =
                make_uint2(*reinterpret_cast<uint32_t*>(&p0),
                           *reinterpret_cast<uint32_t*>(&p1x));
        }

        // Prefetch A(c+1) into regs (hidden under MMA)
        if (c < 7) {
            const int k0n = (c + 1) << 5;
            #pragma unroll
            for (int i = 0; i < 2; i++) {
                int e = tid + (i << 8);
                int r = e >> 3;
                int kk = (e & 7) << 2;
                aReg[i] = *reinterpret_cast<const float4*>(
                    A + (size_t)(row0 + r) * 256 + k0n + kk);
            }
        }

        CP_WAIT0();          // B(c) landed
        __syncthreads();     // A(c)+B(c) visible; all warps done MMA(c-1)

        // Issue B(c+1) after the barrier; overlaps all of MMA(c)
        if (c < 7) {
            issueB((c + 1) << 5, (c + 1) & 1);
            CP_COMMIT();
        }

        const uint32_t uA   = sb + SM_A(c & 1);
        const uint32_t uBhi = sb + SM_B(c & 1);
        const uint32_t uBlo = uBhi + 10240;

        #pragma unroll
        for (int ks = 0; ks < 2; ks++) {
            const int kb = ks << 4;

            uint32_t ah[2][4], bh[2][4];
            #pragma unroll
            for (int mi = 0; mi < 2; mi++) {
                uint32_t addr = uA + (uint32_t)((wm * 32 + mi * 16 + a_row) * LDS_BF + kb + a_koff) * 2;
                ldm_x4(ah[mi], addr);
            }
            #pragma unroll
            for (int g = 0; g < 2; g++) {
                uint32_t roff = (uint32_t)((wn * 32 + g * 16 + b_noff + b_rowsel) * LDS_BF + kb + b_koff) * 2;
                ldm_x4(bh[g], uBhi + roff);
            }
            // term 1: A * B_hi
            #pragma unroll
            for (int mi = 0; mi < 2; mi++)
                #pragma unroll
                for (int ni = 0; ni < 4; ni++) {
                    const uint32_t* bb = bh[ni >> 1];
                    mma16816(acc[mi][ni], ah[mi], bb[(ni & 1) * 2], bb[(ni & 1) * 2 + 1]);
                }
            // term 2: A * B_lo (skipped for 1-term problems)
            if (two) {
                uint32_t bl[2][4];
                #pragma unroll
                for (int g = 0; g < 2; g++) {
                    uint32_t roff = (uint32_t)((wn * 32 + g * 16 + b_noff + b_rowsel) * LDS_BF + kb + b_koff) * 2;
                    ldm_x4(bl[g], uBlo + roff);
                }
                #pragma unroll
                for (int mi = 0; mi < 2; mi++)
                    #pragma unroll
                    for (int ni = 0; ni < 4; ni++) {
                        const uint32_t* bb = bl[ni >> 1];
                        mma16816(acc[mi][ni], ah[mi], bb[(ni & 1) * 2], bb[(ni & 1) * 2 + 1]);
                    }
            }
        }
    }

    const int grp   = lane >> 2;
    const int cpair = (lane & 3) << 1;
    if (halfOut) {
        __half* Ch = (__half*)Cout;
        #pragma unroll
        for (int mi = 0; mi < 2; mi++) {
            #pragma unroll
            for (int ni = 0; ni < 4; ni++) {
                int colg = col0 + wn * 32 + ni * 8 + cpair;
                float b0 = bias[colg], b1 = bias[colg + 1];
                int rowg = row0 + wm * 32 + mi * 16 + grp;
                __half2 o0 = __floats2half2_rn(acc[mi][ni][0] + b0, acc[mi][ni][1] + b1);
                __half2 o1 = __floats2half2_rn(acc[mi][ni][2] + b0, acc[mi][ni][3] + b1);
                *reinterpret_cast<__half2*>(Ch + (size_t)rowg * 256 + colg) = o0;
                *reinterpret_cast<__half2*>(Ch + (size_t)(rowg + 8) * 256 + colg) = o1;
            }
        }
    } else {
        #pragma unroll
        for (int mi = 0; mi < 2; mi++) {
            #pragma unroll
            for (int ni = 0; ni < 4; ni++) {
                int colg = col0 + wn * 32 + ni * 8 + cpair;
                float b0 = bias[colg], b1 = bias[colg + 1];
                int rowg = row0 + wm * 32 + mi * 16 + grp;
                float2 o0 = make_float2(acc[mi][ni][0] + b0, acc[mi][ni][1] + b1);
                float2 o1 = make_float2(acc[mi][ni][2] + b0, acc[mi][ni][3] + b1);
                *reinterpret_cast<float2*>(Cout + (size_t)rowg * 256 + colg) = o0;
                *reinterpret_cast<float2*>(Cout + (size_t)(rowg + 8) * 256 + colg) = o1;
            }
        }
    }
}

// ---------------------------------------------------------------------------
// Fused softmax + loc + deformable gather, TWO queries per 256-thread block
// (round-12 shape, measured best). Phase 1: one thread per (query-half,
// head, point). Phase 2: warp=head, lane=channel, both queries.
// ---------------------------------------------------------------------------
__global__ __launch_bounds__(256) void deform_fused(
    const float* __restrict__ refp,
    float* __restrict__ out_loc,
    float* __restrict__ out_attn)
{
    const int q0 = blockIdx.x << 1;
    const int n  = q0 >> 11;
    const int t  = threadIdx.x;

    __shared__ int4 sPack[256];

    {
        const int q  = q0 + (t >> 7);
        const int tt = t & 127;
        const int l  = (tt >> 2) & 3;
        const float* row = g_offattn + (size_t)q * 256;
        float off  = row[tt];
        float araw = row[128 + tt];

        float mx = araw;
        #pragma unroll
        for (int d = 1; d < 16; d <<= 1)
            mx = fmaxf(mx, __shfl_xor_sync(0xffffffffu, mx, d));
        float e = __expf(araw - mx);
        float s = e;
        #pragma unroll
        for (int d = 1; d < 16; d <<= 1)
            s += __shfl_xor_sync(0xffffffffu, s, d);

        float attn = e / s;
        float loc  = refp[(size_t)q * 4 + l] + off * c_invT[l];

        out_loc [(size_t)q * 128 + tt] = loc;
        out_attn[(size_t)q * 128 + tt] = attn;

        const int Ti = c_tlen[l];
        const int st = c_tstart[l];
        float pos  = loc * (float)Ti - 0.5f;
        float x0f  = floorf(pos);
        float frac = pos - x0f;
        int   x0   = (int)x0f;

        float w0 = (x0 >= 0 && x0 < Ti)         ? (1.0f - frac) * attn : 0.0f;
        float w1 = (x0 + 1 >= 0 && x0 + 1 < Ti) ? frac * attn          : 0.0f;

        int i0 = min(max(x0, 0), Ti - 1) + st;
        int i1 = min(max(x0 + 1, 0), Ti - 1) + st;

        sPack[t] = make_int4(__float_as_int(w0), __float_as_int(w1),
                             i0 << 9, i1 << 9);   // byte offsets (half row = 512 B)
    }
    __syncthreads();

    const int m = t >> 5;
    const int d = t & 31;
    const char* base = (const char*)(g_value_h + (size_t)n * S * C + m * DH + d);

    #pragma unroll
    for (int qi = 0; qi < 2; qi++) {
        const int4* pk = &sPack[(qi << 7) + (m << 4)];
        float acc = 0.0f;
        #pragma unroll
        for (int lp = 0; lp < 16; lp++) {
            int4 p = pk[lp];
            float v0 = __half2float(*reinterpret_cast<const __half*>(base + p.z));
            float v1 = __half2float(*reinterpret_cast<const __half*>(base + p.w));
            acc = fmaf(__int_as_float(p.x), v0, acc);
            acc = fmaf(__int_as_float(p.y), v1, acc);
        }
        g_deform[(size_t)(q0 + qi) * C + t] = acc;
    }
}

// ---------------------------------------------------------------------------
extern "C" void kernel_launch(void* const* d_in, const int* in_sizes, int n_in,
                              void* d_out, int out_size)
{
    const float* query  = (const float*)d_in[0];
    const float* refp   = (const float*)d_in[1];
    const float* inpf   = (const float*)d_in[2];
    const float* W_off  = (const float*)d_in[5];
    const float* b_off  = (const float*)d_in[6];
    const float* W_attn = (const float*)d_in[7];
    const float* b_attn = (const float*)d_in[8];
    const float* W_val  = (const float*)d_in[9];
    const float* b_val  = (const float*)d_in[10];
    const float* W_out  = (const float*)d_in[11];
    const float* b_out  = (const float*)d_in[12];

    float* out      = (float*)d_out;
    float* out_loc  = out + (size_t)NQ * C;
    float* out_attn = out_loc + (size_t)NQ * MLP;

    float *pOffattn, *pDeform, *pBq;
    __half *pValueH, *pWv, *pWq, *pWo;
    cudaGetSymbolAddress((void**)&pValueH,  g_value_h);
    cudaGetSymbolAddress((void**)&pOffattn, g_offattn);
    cudaGetSymbolAddress((void**)&pDeform,  g_deform);
    cudaGetSymbolAddress((void**)&pWv,      g_wv);
    cudaGetSymbolAddress((void**)&pWq,      g_wq);
    cudaGetSymbolAddress((void**)&pWo,      g_wo);
    cudaGetSymbolAddress((void**)&pBq,      g_bq);

    cudaFuncSetAttribute(mma_gemm_bias2, cudaFuncAttributeMaxDynamicSharedMemorySize, GEMM_SMEM);

    // 0) pre-convert weights to fp16 hi/lo
    convert_weights<<<768, 256>>>(W_val, W_off, W_attn, W_out, b_off, b_attn);

    // 1+2) value GEMM (480 blocks, fp16 out, 1-TERM) + off/attn GEMM (256 blocks, 2-term)
    mma_gemm_bias2<<<dim3(2, 736), 256, GEMM_SMEM>>>(
        inpf, pWv, b_val, (float*)pValueH, 480, 1, 1,
        query, pWq, pBq, pOffattn);

    // 3) fused softmax + loc + deformable gather (fp16 value, 2 queries/block)
    deform_fused<<<NQ / 2, 256>>>(refp, out_loc, out_attn);

    // 4) out = g_deform @ W_out + b_out  (256 blocks, 2-term)
    mma_gemm_bias2<<<dim3(2, 256), 256, GEMM_SMEM>>>(
        pDeform, pWo, b_out, out, 256, 0, 2,
        pDeform, pWo, b_out, out);
}

// round 16
// speedup vs baseline: 1.2992x; 1.0756x over previous
#include <cuda_runtime.h>
#include <cuda_bf16.h>
#include <cuda_fp16.h>
#include <cstdint>

// Problem constants (static per reference)
#define NB   8
#define LQ   2048
#define C    256
#define M    8
#define L    4
#define P    4
#define DH   32
#define S    3840
#define NQ   (NB * LQ)          // 16384
#define MLP  (M * L * P)        // 128

__device__ __constant__ int   c_tlen[4]   = {2048, 1024, 512, 256};
__device__ __constant__ int   c_tstart[4] = {0, 2048, 3072, 3584};
__device__ __constant__ float c_invT[4]   = {1.0f/2048.0f, 1.0f/1024.0f, 1.0f/512.0f, 1.0f/256.0f};

// Scratch (device globals — no allocation allowed)
__device__ __half g_value_h[NB * S * C];  // value in fp16 (consumed only by deform)
__device__ float g_offattn[NQ * 256];     // [0:128)=off raw, [128:256)=attn raw
__device__ float g_deform[NQ * C];

// Pre-converted weights: transposed (n, k=256) fp16; hi plane then lo plane
__device__ __half g_wv[2 * 256 * 256];
__device__ __half g_wq[2 * 256 * 256];
__device__ __half g_wo[2 * 256 * 256];
__device__ float  g_bq[256];

// ===========================================================================
// Helpers
// ===========================================================================
__device__ __forceinline__ uint32_t smem_u32(const void* p) {
    uint32_t a;
    asm("{ .reg .u64 t; cvta.to.shared.u64 t, %1; cvt.u32.u64 %0, t; }" : "=r"(a) : "l"(p));
    return a;
}

__device__ __forceinline__ void ldm_x4(uint32_t* r, uint32_t addr) {
    asm volatile("ldmatrix.sync.aligned.m8n8.x4.shared.b16 {%0,%1,%2,%3}, [%4];"
                 : "=r"(r[0]), "=r"(r[1]), "=r"(r[2]), "=r"(r[3]) : "r"(addr));
}

__device__ __forceinline__ void mma16816(float* c, const uint32_t* a, uint32_t b0, uint32_t b1) {
    asm volatile("mma.sync.aligned.m16n8k16.row.col.f32.f16.f16.f32 "
                 "{%0,%1,%2,%3}, {%4,%5,%6,%7}, {%8,%9}, {%0,%1,%2,%3};"
                 : "+f"(c[0]), "+f"(c[1]), "+f"(c[2]), "+f"(c[3])
                 : "r"(a[0]), "r"(a[1]), "r"(a[2]), "r"(a[3]), "r"(b0), "r"(b1));
}

#define CP_ASYNC16(dst, src) \
    asm volatile("cp.async.cg.shared.global [%0], [%1], 16;" :: "r"(dst), "l"(src))
#define CP_COMMIT() asm volatile("cp.async.commit_group;" ::: "memory")
#define CP_WAIT0()  asm volatile("cp.async.wait_group 0;" ::: "memory")

// ===========================================================================
// Weight pre-conversion: W (k-major fp32) -> W^T (n,256) fp16 hi + fp16 lo.
// ===========================================================================
__global__ __launch_bounds__(256) void convert_weights(
    const float* __restrict__ Wv, const float* __restrict__ Woff,
    const float* __restrict__ Wattn, const float* __restrict__ Wo,
    const float* __restrict__ boff, const float* __restrict__ battn)
{
    int idx = blockIdx.x * 256 + threadIdx.x;
    int mat = idx >> 16;
    int r   = idx & 65535;
    int n   = r >> 8;
    int k   = r & 255;

    float v;
    if (mat == 0)      v = Wv[k * 256 + n];
    else if (mat == 1) v = (n < 128) ? Woff[k * 128 + n] : Wattn[k * 128 + (n - 128)];
    else               v = Wo[k * 256 + n];

    __half h = __float2half_rn(v);
    __half l = __float2half_rn(v - __half2float(h));

    __half* base = (mat == 0) ? g_wv : (mat == 1) ? g_wq : g_wo;
    base[n * 256 + k]         = h;
    base[65536 + n * 256 + k] = l;

    if (mat == 1 && k == 0)
        g_bq[n] = (n < 128) ? boff[n] : battn[n - 128];
}

// ===========================================================================
// Pipelined fp16 tensor-core GEMM, 64x128 tile, dual problem set.
// Template T1/T2 = MMA terms per problem (compile-time; 1 = A@B_hi only,
// 2 = A@(B_hi+B_lo)). (256,3): 80 regs is the natural operating point.
// ONE barrier per K-chunk; A single fp16 plane double-buffered; B via
// cp.async double buffer (lo plane skipped when 1-term).
// ===========================================================================
#define LDS_BF 40
#define SM_A(s) ((s) * 5120)             // single fp16 plane, 64 x 80 B
#define SM_B(s) (10240 + (s) * 20480)    // planes: hi +0, lo +10240
#define GEMM_SMEM 51200

template<int T1, int T2>
__global__ void __launch_bounds__(256, 3) mma_gemm_bias2(
    const float* __restrict__ A1, const __half* __restrict__ Wt1,
    const float* __restrict__ bias1, float* __restrict__ C1, int nby1, int half1,
    const float* __restrict__ A2, const __half* __restrict__ Wt2,
    const float* __restrict__ bias2, float* __restrict__ C2)
{
    extern __shared__ __align__(128) char smem[];
    const uint32_t sb = smem_u32(smem);

    const int by = blockIdx.y;
    const bool p1 = (by < nby1);
    const float*  A    = p1 ? A1    : A2;
    const __half* Wt   = p1 ? Wt1   : Wt2;
    const float*  bias = p1 ? bias1 : bias2;
    float*        Cout = p1 ? C1    : C2;
    const bool halfOut = p1 && half1;
    const bool two     = (T1 == T2) ? (T1 == 2) : (p1 ? (T1 == 2) : (T2 == 2));

    const int tid  = threadIdx.x;
    const int wid  = tid >> 5;
    const int lane = tid & 31;
    const int row0 = (p1 ? by : (by - nby1)) * 64;
    const int col0 = blockIdx.x * 128;
    const int wm   = wid & 1;
    const int wn   = wid >> 1;

    float acc[2][4][4];
    #pragma unroll
    for (int i = 0; i < 2; i++)
        #pragma unroll
        for (int j = 0; j < 4; j++)
            #pragma unroll
            for (int r = 0; r < 4; r++) acc[i][j][r] = 0.0f;

    const int a_row    = lane & 15;
    const int a_koff   = (lane >> 4) << 3;
    const int b_rowsel = lane & 7;
    const int b_koff   = ((lane >> 3) & 1) << 3;
    const int b_noff   = (lane >> 4) << 3;

    const int nld = two ? 4 : 2;     // cp.async quads per thread (hi+lo or hi)
    auto issueB = [&](int k0, int st) {
        #pragma unroll 4
        for (int i = 0; i < nld; i++) {
            int e   = tid + (i << 8);
            int buf = e >> 9;               // 0 hi, 1 lo
            int r   = (e >> 2) & 127;
            int q16 = e & 3;
            const __half* src =
                Wt + (size_t)buf * 65536 + (size_t)(col0 + r) * 256 + k0 + (q16 << 3);
            uint32_t dst = sb + SM_B(st) + buf * 10240 + r * 80 + (q16 << 4);
            CP_ASYNC16(dst, src);
        }
    };

    // Prologue: A chunk 0 -> regs, B chunk 0 -> stage 0
    float4 aReg[2];
    #pragma unroll
    for (int i = 0; i < 2; i++) {
        int e = tid + (i << 8);
        int r = e >> 3;
        int kk = (e & 7) << 2;
        aReg[i] = *reinterpret_cast<const float4*>(A + (size_t)(row0 + r) * 256 + kk);
    }
    issueB(0, 0);
    CP_COMMIT();

    for (int c = 0; c < 8; c++) {
        // cvt + store A(c) into bufA[c&1]
        #pragma unroll
        for (int i = 0; i < 2; i++) {
            int e = tid + (i << 8);
            int r = e >> 3;
            int kk = (e & 7) << 2;
            __half2 p0 = __floats2half2_rn(aReg[i].x, aReg[i].y);
            __half2 p1x = __floats2half2_rn(aReg[i].z, aReg[i].w);
            uint32_t off = (uint32_t)(r * LDS_BF + kk) * 2;
            *reinterpret_cast<uint2*>(smem + SM_A(c & 1) + off) =
                make_uint2(*reinterpret_cast<uint32_t*>(&p0),
                           *reinterpret_cast<uint32_t*>(&p1x));
        }

        // Prefetch A(c+1) into regs (hidden under MMA)
        if (c < 7) {
            const int k0n = (c + 1) << 5;
            #pragma unroll
            for (int i = 0; i < 2; i++) {
                int e = tid + (i << 8);
                int r = e >> 3;
                int kk = (e & 7) << 2;
                aReg[i] = *reinterpret_cast<const float4*>(
                    A + (size_t)(row0 + r) * 256 + k0n + kk);
            }
        }

        CP_WAIT0();          // B(c) landed
        __syncthreads();     // A(c)+B(c) visible; all warps done MMA(c-1)

        // Issue B(c+1) after the barrier; overlaps all of MMA(c)
        if (c < 7) {
            issueB((c + 1) << 5, (c + 1) & 1);
            CP_COMMIT();
        }

        const uint32_t uA   = sb + SM_A(c & 1);
        const uint32_t uBhi = sb + SM_B(c & 1);
        const uint32_t uBlo = uBhi + 10240;

        #pragma unroll
        for (int ks = 0; ks < 2; ks++) {
            const int kb = ks << 4;

            uint32_t ah[2][4], bh[2][4];
            #pragma unroll
            for (int mi = 0; mi < 2; mi++) {
                uint32_t addr = uA + (uint32_t)((wm * 32 + mi * 16 + a_row) * LDS_BF + kb + a_koff) * 2;
                ldm_x4(ah[mi], addr);
            }
            #pragma unroll
            for (int g = 0; g < 2; g++) {
                uint32_t roff = (uint32_t)((wn * 32 + g * 16 + b_noff + b_rowsel) * LDS_BF + kb + b_koff) * 2;
                ldm_x4(bh[g], uBhi + roff);
            }
            // term 1: A * B_hi
            #pragma unroll
            for (int mi = 0; mi < 2; mi++)
                #pragma unroll
                for (int ni = 0; ni < 4; ni++) {
                    const uint32_t* bb = bh[ni >> 1];
                    mma16816(acc[mi][ni], ah[mi], bb[(ni & 1) * 2], bb[(ni & 1) * 2 + 1]);
                }
            // term 2: A * B_lo (compile-time-eliminated for pure 1-term)
            if (two) {
                uint32_t bl[2][4];
                #pragma unroll
                for (int g = 0; g < 2; g++) {
                    uint32_t roff = (uint32_t)((wn * 32 + g * 16 + b_noff + b_rowsel) * LDS_BF + kb + b_koff) * 2;
                    ldm_x4(bl[g], uBlo + roff);
                }
                #pragma unroll
                for (int mi = 0; mi < 2; mi++)
                    #pragma unroll
                    for (int ni = 0; ni < 4; ni++) {
                        const uint32_t* bb = bl[ni >> 1];
                        mma16816(acc[mi][ni], ah[mi], bb[(ni & 1) * 2], bb[(ni & 1) * 2 + 1]);
                    }
            }
        }
    }

    const int grp   = lane >> 2;
    const int cpair = (lane & 3) << 1;
    if (halfOut) {
        __half* Ch = (__half*)Cout;
        #pragma unroll
        for (int mi = 0; mi < 2; mi++) {
            #pragma unroll
            for (int ni = 0; ni < 4; ni++) {
                int colg = col0 + wn * 32 + ni * 8 + cpair;
                float b0 = bias[colg], b1 = bias[colg + 1];
                int rowg = row0 + wm * 32 + mi * 16 + grp;
                __half2 o0 = __floats2half2_rn(acc[mi][ni][0] + b0, acc[mi][ni][1] + b1);
                __half2 o1 = __floats2half2_rn(acc[mi][ni][2] + b0, acc[mi][ni][3] + b1);
                *reinterpret_cast<__half2*>(Ch + (size_t)rowg * 256 + colg) = o0;
                *reinterpret_cast<__half2*>(Ch + (size_t)(rowg + 8) * 256 + colg) = o1;
            }
        }
    } else {
        #pragma unroll
        for (int mi = 0; mi < 2; mi++) {
            #pragma unroll
            for (int ni = 0; ni < 4; ni++) {
                int colg = col0 + wn * 32 + ni * 8 + cpair;
                float b0 = bias[colg], b1 = bias[colg + 1];
                int rowg = row0 + wm * 32 + mi * 16 + grp;
                float2 o0 = make_float2(acc[mi][ni][0] + b0, acc[mi][ni][1] + b1);
                float2 o1 = make_float2(acc[mi][ni][2] + b0, acc[mi][ni][3] + b1);
                *reinterpret_cast<float2*>(Cout + (size_t)rowg * 256 + colg) = o0;
                *reinterpret_cast<float2*>(Cout + (size_t)(rowg + 8) * 256 + colg) = o1;
            }
        }
    }
}

// ---------------------------------------------------------------------------
// Fused softmax + loc + deformable gather, TWO queries per 256-thread block.
// ---------------------------------------------------------------------------
__global__ __launch_bounds__(256) void deform_fused(
    const float* __restrict__ refp,
    float* __restrict__ out_loc,
    float* __restrict__ out_attn)
{
    const int q0 = blockIdx.x << 1;
    const int n  = q0 >> 11;
    const int t  = threadIdx.x;

    __shared__ int4 sPack[256];

    {
        const int q  = q0 + (t >> 7);
        const int tt = t & 127;
        const int l  = (tt >> 2) & 3;
        const float* row = g_offattn + (size_t)q * 256;
        float off  = row[tt];
        float araw = row[128 + tt];

        float mx = araw;
        #pragma unroll
        for (int d = 1; d < 16; d <<= 1)
            mx = fmaxf(mx, __shfl_xor_sync(0xffffffffu, mx, d));
        float e = __expf(araw - mx);
        float s = e;
        #pragma unroll
        for (int d = 1; d < 16; d <<= 1)
            s += __shfl_xor_sync(0xffffffffu, s, d);

        float attn = e / s;
        float loc  = refp[(size_t)q * 4 + l] + off * c_invT[l];

        out_loc [(size_t)q * 128 + tt] = loc;
        out_attn[(size_t)q * 128 + tt] = attn;

        const int Ti = c_tlen[l];
        const int st = c_tstart[l];
        float pos  = loc * (float)Ti - 0.5f;
        float x0f  = floorf(pos);
        float frac = pos - x0f;
        int   x0   = (int)x0f;

        float w0 = (x0 >= 0 && x0 < Ti)         ? (1.0f - frac) * attn : 0.0f;
        float w1 = (x0 + 1 >= 0 && x0 + 1 < Ti) ? frac * attn          : 0.0f;

        int i0 = min(max(x0, 0), Ti - 1) + st;
        int i1 = min(max(x0 + 1, 0), Ti - 1) + st;

        sPack[t] = make_int4(__float_as_int(w0), __float_as_int(w1),
                             i0 << 9, i1 << 9);   // byte offsets (half row = 512 B)
    }
    __syncthreads();

    const int m = t >> 5;
    const int d = t & 31;
    const char* base = (const char*)(g_value_h + (size_t)n * S * C + m * DH + d);

    #pragma unroll
    for (int qi = 0; qi < 2; qi++) {
        const int4* pk = &sPack[(qi << 7) + (m << 4)];
        float acc = 0.0f;
        #pragma unroll
        for (int lp = 0; lp < 16; lp++) {
            int4 p = pk[lp];
            float v0 = __half2float(*reinterpret_cast<const __half*>(base + p.z));
            float v1 = __half2float(*reinterpret_cast<const __half*>(base + p.w));
            acc = fmaf(__int_as_float(p.x), v0, acc);
            acc = fmaf(__int_as_float(p.y), v1, acc);
        }
        g_deform[(size_t)(q0 + qi) * C + t] = acc;
    }
}

// ---------------------------------------------------------------------------
extern "C" void kernel_launch(void* const* d_in, const int* in_sizes, int n_in,
                              void* d_out, int out_size)
{
    const float* query  = (const float*)d_in[0];
    const float* refp   = (const float*)d_in[1];
    const float* inpf   = (const float*)d_in[2];
    const float* W_off  = (const float*)d_in[5];
    const float* b_off  = (const float*)d_in[6];
    const float* W_attn = (const float*)d_in[7];
    const float* b_attn = (const float*)d_in[8];
    const float* W_val  = (const float*)d_in[9];
    const float* b_val  = (const float*)d_in[10];
    const float* W_out  = (const float*)d_in[11];
    const float* b_out  = (const float*)d_in[12];

    float* out      = (float*)d_out;
    float* out_loc  = out + (size_t)NQ * C;
    float* out_attn = out_loc + (size_t)NQ * MLP;

    float *pOffattn, *pDeform, *pBq;
    __half *pValueH, *pWv, *pWq, *pWo;
    cudaGetSymbolAddress((void**)&pValueH,  g_value_h);
    cudaGetSymbolAddress((void**)&pOffattn, g_offattn);
    cudaGetSymbolAddress((void**)&pDeform,  g_deform);
    cudaGetSymbolAddress((void**)&pWv,      g_wv);
    cudaGetSymbolAddress((void**)&pWq,      g_wq);
    cudaGetSymbolAddress((void**)&pWo,      g_wo);
    cudaGetSymbolAddress((void**)&pBq,      g_bq);

    cudaFuncSetAttribute(mma_gemm_bias2<1, 2>, cudaFuncAttributeMaxDynamicSharedMemorySize, GEMM_SMEM);
    cudaFuncSetAttribute(mma_gemm_bias2<1, 1>, cudaFuncAttributeMaxDynamicSharedMemorySize, GEMM_SMEM);

    // 0) pre-convert weights to fp16 hi/lo
    convert_weights<<<768, 256>>>(W_val, W_off, W_attn, W_out, b_off, b_attn);

    // 1+2) value GEMM (480 blocks, fp16 out, 1-TERM) + off/attn GEMM (256 blocks, 2-term)
    mma_gemm_bias2<1, 2><<<dim3(2, 736), 256, GEMM_SMEM>>>(
        inpf, pWv, b_val, (float*)pValueH, 480, 1,
        query, pWq, pBq, pOffattn);

    // 3) fused softmax + loc + deformable gather (fp16 value, 2 queries/block)
    deform_fused<<<NQ / 2, 256>>>(refp, out_loc, out_attn);

    // 4) out = g_deform @ W_out + b_out  (256 blocks, 1-TERM, branchless)
    mma_gemm_bias2<1, 1><<<dim3(2, 256), 256, GEMM_SMEM>>>(
        pDeform, pWo, b_out, out, 256, 0,
        pDeform, pWo, b_out, out);
}

// round 17
// speedup vs baseline: 1.5047x; 1.1581x over previous
#include <cuda_runtime.h>
#include <cuda_bf16.h>
#include <cuda_fp16.h>
#include <cstdint>

// Problem constants (static per reference)
#define NB   8
#define LQ   2048
#define C    256
#define M    8
#define L    4
#define P    4
#define DH   32
#define S    3840
#define NQ   (NB * LQ)          // 16384
#define MLP  (M * L * P)        // 128

__device__ __constant__ int   c_tlen[4]   = {2048, 1024, 512, 256};
__device__ __constant__ int   c_tstart[4] = {0, 2048, 3072, 3584};
__device__ __constant__ float c_invT[4]   = {1.0f/2048.0f, 1.0f/1024.0f, 1.0f/512.0f, 1.0f/256.0f};

// Scratch (device globals — no allocation allowed)
__device__ __half g_value_h[NB * S * C];  // value in fp16 (consumed only by deform)
__device__ float g_offattn[NQ * 256];     // [0:128)=off raw, [128:256)=attn raw
__device__ float g_deform[NQ * C];

// Pre-converted weights: transposed (n, k=256) fp16 (hi only; 1-term GEMMs)
__device__ __half g_wv[256 * 256];
__device__ __half g_wq[256 * 256];
__device__ __half g_wo[256 * 256];
__device__ float  g_bq[256];

// ===========================================================================
// Helpers
// ===========================================================================
__device__ __forceinline__ uint32_t smem_u32(const void* p) {
    uint32_t a;
    asm("{ .reg .u64 t; cvta.to.shared.u64 t, %1; cvt.u32.u64 %0, t; }" : "=r"(a) : "l"(p));
    return a;
}

__device__ __forceinline__ void ldm_x4(uint32_t* r, uint32_t addr) {
    asm volatile("ldmatrix.sync.aligned.m8n8.x4.shared.b16 {%0,%1,%2,%3}, [%4];"
                 : "=r"(r[0]), "=r"(r[1]), "=r"(r[2]), "=r"(r[3]) : "r"(addr));
}

__device__ __forceinline__ void mma16816(float* c, const uint32_t* a, uint32_t b0, uint32_t b1) {
    asm volatile("mma.sync.aligned.m16n8k16.row.col.f32.f16.f16.f32 "
                 "{%0,%1,%2,%3}, {%4,%5,%6,%7}, {%8,%9}, {%0,%1,%2,%3};"
                 : "+f"(c[0]), "+f"(c[1]), "+f"(c[2]), "+f"(c[3])
                 : "r"(a[0]), "r"(a[1]), "r"(a[2]), "r"(a[3]), "r"(b0), "r"(b1));
}

#define CP_ASYNC16(dst, src) \
    asm volatile("cp.async.cg.shared.global [%0], [%1], 16;" :: "r"(dst), "l"(src))
#define CP_COMMIT() asm volatile("cp.async.commit_group;" ::: "memory")
#define CP_WAIT0()  asm volatile("cp.async.wait_group 0;" ::: "memory")

// ===========================================================================
// Weight pre-conversion: W (k-major fp32) -> W^T (n,256) fp16 (hi only).
// ===========================================================================
__global__ __launch_bounds__(256) void convert_weights(
    const float* __restrict__ Wv, const float* __restrict__ Woff,
    const float* __restrict__ Wattn, const float* __restrict__ Wo,
    const float* __restrict__ boff, const float* __restrict__ battn)
{
    int idx = blockIdx.x * 256 + threadIdx.x;
    int mat = idx >> 16;
    int r   = idx & 65535;
    int n   = r >> 8;
    int k   = r & 255;

    float v;
    if (mat == 0)      v = Wv[k * 256 + n];
    else if (mat == 1) v = (n < 128) ? Woff[k * 128 + n] : Wattn[k * 128 + (n - 128)];
    else               v = Wo[k * 256 + n];

    __half* base = (mat == 0) ? g_wv : (mat == 1) ? g_wq : g_wo;
    base[n * 256 + k] = __float2half_rn(v);

    if (mat == 1 && k == 0)
        g_bq[n] = (n < 128) ? boff[n] : battn[n - 128];
}

// ===========================================================================
// Pipelined fp16 1-term tensor-core GEMM, 64x128 tile, dual problem set.
// C = A_f16 @ W_f16 + bias, fp32 accumulate. (256,3): 80 regs is the natural
// operating point. ONE barrier per K-chunk; A single fp16 plane double-
// buffered; B hi plane via cp.async double buffer. Smem 30 KB/CTA.
// ===========================================================================
#define LDS_BF 40
#define SM_A(s) ((s) * 5120)             // A fp16 plane, 64 x 80 B
#define SM_B(s) (10240 + (s) * 10240)    // B hi plane, 128 x 80 B
#define GEMM_SMEM 30720

__global__ void __launch_bounds__(256, 3) mma_gemm_bias2(
    const float* __restrict__ A1, const __half* __restrict__ Wt1,
    const float* __restrict__ bias1, float* __restrict__ C1, int nby1, int half1,
    const float* __restrict__ A2, const __half* __restrict__ Wt2,
    const float* __restrict__ bias2, float* __restrict__ C2)
{
    extern __shared__ __align__(128) char smem[];
    const uint32_t sb = smem_u32(smem);

    const int by = blockIdx.y;
    const bool p1 = (by < nby1);
    const float*  A    = p1 ? A1    : A2;
    const __half* Wt   = p1 ? Wt1   : Wt2;
    const float*  bias = p1 ? bias1 : bias2;
    float*        Cout = p1 ? C1    : C2;
    const bool halfOut = p1 && half1;

    const int tid  = threadIdx.x;
    const int wid  = tid >> 5;
    const int lane = tid & 31;
    const int row0 = (p1 ? by : (by - nby1)) * 64;
    const int col0 = blockIdx.x * 128;
    const int wm   = wid & 1;
    const int wn   = wid >> 1;

    float acc[2][4][4];
    #pragma unroll
    for (int i = 0; i < 2; i++)
        #pragma unroll
        for (int j = 0; j < 4; j++)
            #pragma unroll
            for (int r = 0; r < 4; r++) acc[i][j][r] = 0.0f;

    const int a_row    = lane & 15;
    const int a_koff   = (lane >> 4) << 3;
    const int b_rowsel = lane & 7;
    const int b_koff   = ((lane >> 3) & 1) << 3;
    const int b_noff   = (lane >> 4) << 3;

    auto issueB = [&](int k0, int st) {
        #pragma unroll
        for (int i = 0; i < 2; i++) {
            int e   = tid + (i << 8);        // 0..511 quads (hi plane only)
            int r   = (e >> 2) & 127;
            int q16 = e & 3;
            const __half* src =
                Wt + (size_t)(col0 + r) * 256 + k0 + (q16 << 3);
            uint32_t dst = sb + SM_B(st) + r * 80 + (q16 << 4);
            CP_ASYNC16(dst, src);
        }
    };

    // Prologue: A chunk 0 -> regs, B chunk 0 -> stage 0
    float4 aReg[2];
    #pragma unroll
    for (int i = 0; i < 2; i++) {
        int e = tid + (i << 8);
        int r = e >> 3;
        int kk = (e & 7) << 2;
        aReg[i] = *reinterpret_cast<const float4*>(A + (size_t)(row0 + r) * 256 + kk);
    }
    issueB(0, 0);
    CP_COMMIT();

    for (int c = 0; c < 8; c++) {
        // cvt + store A(c) into bufA[c&1]
        #pragma unroll
        for (int i = 0; i < 2; i++) {
            int e = tid + (i << 8);
            int r = e >> 3;
            int kk = (e & 7) << 2;
            __half2 p0 = __floats2half2_rn(aReg[i].x, aReg[i].y);
            __half2 p1x = __floats2half2_rn(aReg[i].z, aReg[i].w);
            uint32_t off = (uint32_t)(r * LDS_BF + kk) * 2;
            *reinterpret_cast<uint2*>(smem + SM_A(c & 1) + off) =
                make_uint2(*reinterpret_cast<uint32_t*>(&p0),
                           *reinterpret_cast<uint32_t*>(&p1x));
        }

        // Prefetch A(c+1) into regs (hidden under MMA)
        if (c < 7) {
            const int k0n = (c + 1) << 5;
            #pragma unroll
            for (int i = 0; i < 2; i++) {
                int e = tid + (i << 8);
                int r = e >> 3;
                int kk = (e & 7) << 2;
                aReg[i] = *reinterpret_cast<const float4*>(
                    A + (size_t)(row0 + r) * 256 + k0n + kk);
            }
        }

        CP_WAIT0();          // B(c) landed
        __syncthreads();     // A(c)+B(c) visible; all warps done MMA(c-1)

        // Issue B(c+1) after the barrier; overlaps all of MMA(c)
        if (c < 7) {
            issueB((c + 1) << 5, (c + 1) & 1);
            CP_COMMIT();
        }

        const uint32_t uA   = sb + SM_A(c & 1);
        const uint32_t uBhi = sb + SM_B(c & 1);

        #pragma unroll
        for (int ks = 0; ks < 2; ks++) {
            const int kb = ks << 4;

            uint32_t ah[2][4], bh[2][4];
            #pragma unroll
            for (int mi = 0; mi < 2; mi++) {
                uint32_t addr = uA + (uint32_t)((wm * 32 + mi * 16 + a_row) * LDS_BF + kb + a_koff) * 2;
                ldm_x4(ah[mi], addr);
            }
            #pragma unroll
            for (int g = 0; g < 2; g++) {
                uint32_t roff = (uint32_t)((wn * 32 + g * 16 + b_noff + b_rowsel) * LDS_BF + kb + b_koff) * 2;
                ldm_x4(bh[g], uBhi + roff);
            }
            #pragma unroll
            for (int mi = 0; mi < 2; mi++)
                #pragma unroll
                for (int ni = 0; ni < 4; ni++) {
                    const uint32_t* bb = bh[ni >> 1];
                    mma16816(acc[mi][ni], ah[mi], bb[(ni & 1) * 2], bb[(ni & 1) * 2 + 1]);
                }
        }
    }

    const int grp   = lane >> 2;
    const int cpair = (lane & 3) << 1;
    if (halfOut) {
        __half* Ch = (__half*)Cout;
        #pragma unroll
        for (int mi = 0; mi < 2; mi++) {
            #pragma unroll
            for (int ni = 0; ni < 4; ni++) {
                int colg = col0 + wn * 32 + ni * 8 + cpair;
                float b0 = bias[colg], b1 = bias[colg + 1];
                int rowg = row0 + wm * 32 + mi * 16 + grp;
                __half2 o0 = __floats2half2_rn(acc[mi][ni][0] + b0, acc[mi][ni][1] + b1);
                __half2 o1 = __floats2half2_rn(acc[mi][ni][2] + b0, acc[mi][ni][3] + b1);
                *reinterpret_cast<__half2*>(Ch + (size_t)rowg * 256 + colg) = o0;
                *reinterpret_cast<__half2*>(Ch + (size_t)(rowg + 8) * 256 + colg) = o1;
            }
        }
    } else {
        #pragma unroll
        for (int mi = 0; mi < 2; mi++) {
            #pragma unroll
            for (int ni = 0; ni < 4; ni++) {
                int colg = col0 + wn * 32 + ni * 8 + cpair;
                float b0 = bias[colg], b1 = bias[colg + 1];
                int rowg = row0 + wm * 32 + mi * 16 + grp;
                float2 o0 = make_float2(acc[mi][ni][0] + b0, acc[mi][ni][1] + b1);
                float2 o1 = make_float2(acc[mi][ni][2] + b0, acc[mi][ni][3] + b1);
                *reinterpret_cast<float2*>(Cout + (size_t)rowg * 256 + colg) = o0;
                *reinterpret_cast<float2*>(Cout + (size_t)(rowg + 8) * 256 + colg) = o1;
            }
        }
    }
}

// ---------------------------------------------------------------------------
// Fused softmax + loc + deformable gather, TWO queries per 256-thread block.
// Phase 1: one thread per (query-half, head, point): softmax, loc, and
// index/weight precompute packed in smem.
// Phase 2: warp = head; lanes 0-15 query 0, lanes 16-31 query 1; each lane
// covers a channel PAIR via one __half2 load (halves LDG count vs U16).
// ---------------------------------------------------------------------------
__global__ __launch_bounds__(256) void deform_fused(
    const float* __restrict__ refp,
    float* __restrict__ out_loc,
    float* __restrict__ out_attn)
{
    const int q0 = blockIdx.x << 1;
    const int n  = q0 >> 11;
    const int t  = threadIdx.x;

    __shared__ int4 sPack[256];

    {
        const int q  = q0 + (t >> 7);
        const int tt = t & 127;
        const int l  = (tt >> 2) & 3;
        const float* row = g_offattn + (size_t)q * 256;
        float off  = row[tt];
        float araw = row[128 + tt];

        float mx = araw;
        #pragma unroll
        for (int d = 1; d < 16; d <<= 1)
            mx = fmaxf(mx, __shfl_xor_sync(0xffffffffu, mx, d));
        float e = __expf(araw - mx);
        float s = e;
        #pragma unroll
        for (int d = 1; d < 16; d <<= 1)
            s += __shfl_xor_sync(0xffffffffu, s, d);

        float attn = e / s;
        float loc  = refp[(size_t)q * 4 + l] + off * c_invT[l];

        out_loc [(size_t)q * 128 + tt] = loc;
        out_attn[(size_t)q * 128 + tt] = attn;

        const int Ti = c_tlen[l];
        const int st = c_tstart[l];
        float pos  = loc * (float)Ti - 0.5f;
        float x0f  = floorf(pos);
        float frac = pos - x0f;
        int   x0   = (int)x0f;

        float w0 = (x0 >= 0 && x0 < Ti)         ? (1.0f - frac) * attn : 0.0f;
        float w1 = (x0 + 1 >= 0 && x0 + 1 < Ti) ? frac * attn          : 0.0f;

        int i0 = min(max(x0, 0), Ti - 1) + st;
        int i1 = min(max(x0 + 1, 0), Ti - 1) + st;

        sPack[t] = make_int4(__float_as_int(w0), __float_as_int(w1),
                             i0 << 9, i1 << 9);   // byte offsets (half row = 512 B)
    }
    __syncthreads();

    const int m    = t >> 5;              // warp = head
    const int lane = t & 31;
    const int qi   = lane >> 4;           // query half
    const int ch   = (lane & 15) << 1;    // channel pair base
    const char* base = (const char*)g_value_h +
        ((size_t)n * S * C + m * DH + ch) * 2;
    const int4* pk = &sPack[(qi << 7) + (m << 4)];

    float2 accA = make_float2(0.0f, 0.0f);
    float2 accB = make_float2(0.0f, 0.0f);
    #pragma unroll
    for (int lp = 0; lp < 16; lp += 2) {
        int4 pa = pk[lp];
        int4 pb = pk[lp + 1];
        float2 a0 = __half22float2(*reinterpret_cast<const __half2*>(base + pa.z));
        float2 a1 = __half22float2(*reinterpret_cast<const __half2*>(base + pa.w));
        float2 b0 = __half22float2(*reinterpret_cast<const __half2*>(base + pb.z));
        float2 b1 = __half22float2(*reinterpret_cast<const __half2*>(base + pb.w));
        float wa0 = __int_as_float(pa.x), wa1 = __int_as_float(pa.y);
        float wb0 = __int_as_float(pb.x), wb1 = __int_as_float(pb.y);
        accA.x = fmaf(wa0, a0.x, accA.x); accA.y = fmaf(wa0, a0.y, accA.y);
        accA.x = fmaf(wa1, a1.x, accA.x); accA.y = fmaf(wa1, a1.y, accA.y);
        accB.x = fmaf(wb0, b0.x, accB.x); accB.y = fmaf(wb0, b0.y, accB.y);
        accB.x = fmaf(wb1, b1.x, accB.x); accB.y = fmaf(wb1, b1.y, accB.y);
    }

    float2 o = make_float2(accA.x + accB.x, accA.y + accB.y);
    *reinterpret_cast<float2*>(g_deform + (size_t)(q0 + qi) * C + m * DH + ch) = o;
}

// ---------------------------------------------------------------------------
extern "C" void kernel_launch(void* const* d_in, const int* in_sizes, int n_in,
                              void* d_out, int out_size)
{
    const float* query  = (const float*)d_in[0];
    const float* refp   = (const float*)d_in[1];
    const float* inpf   = (const float*)d_in[2];
    const float* W_off  = (const float*)d_in[5];
    const float* b_off  = (const float*)d_in[6];
    const float* W_attn = (const float*)d_in[7];
    const float* b_attn = (const float*)d_in[8];
    const float* W_val  = (const float*)d_in[9];
    const float* b_val  = (const float*)d_in[10];
    const float* W_out  = (const float*)d_in[11];
    const float* b_out  = (const float*)d_in[12];

    float* out      = (float*)d_out;
    float* out_loc  = out + (size_t)NQ * C;
    float* out_attn = out_loc + (size_t)NQ * MLP;

    float *pOffattn, *pDeform, *pBq;
    __half *pValueH, *pWv, *pWq, *pWo;
    cudaGetSymbolAddress((void**)&pValueH,  g_value_h);
    cudaGetSymbolAddress((void**)&pOffattn, g_offattn);
    cudaGetSymbolAddress((void**)&pDeform,  g_deform);
    cudaGetSymbolAddress((void**)&pWv,      g_wv);
    cudaGetSymbolAddress((void**)&pWq,      g_wq);
    cudaGetSymbolAddress((void**)&pWo,      g_wo);
    cudaGetSymbolAddress((void**)&pBq,      g_bq);

    cudaFuncSetAttribute(mma_gemm_bias2, cudaFuncAttributeMaxDynamicSharedMemorySize, GEMM_SMEM);

    // 0) pre-convert weights to fp16 (hi only)
    convert_weights<<<768, 256>>>(W_val, W_off, W_attn, W_out, b_off, b_attn);

    // 1+2) value GEMM (480 blocks, fp16 out) + off/attn GEMM (256 blocks), all 1-term
    mma_gemm_bias2<<<dim3(2, 736), 256, GEMM_SMEM>>>(
        inpf, pWv, b_val, (float*)pValueH, 480, 1,
        query, pWq, pBq, pOffattn);

    // 3) fused softmax + loc + deformable gather (fp16 value, half2 gathers)
    deform_fused<<<NQ / 2, 256>>>(refp, out_loc, out_attn);

    // 4) out = g_deform @ W_out + b_out  (256 blocks, 1-term)
    mma_gemm_bias2<<<dim3(2, 256), 256, GEMM_SMEM>>>(
        pDeform, pWo, b_out, out, 256, 0,
        pDeform, pWo, b_out, out);
}